// round 1
// baseline (speedup 1.0000x reference)
#include <cuda_runtime.h>
#include <cuda_bf16.h>

// SSM scan: h_t = A_t * h_{t-1} + B_t * x_t ;  y_t[d] = sum_n C_t[n] * h_t[d,n]
// Shapes: A,B [b=2, s=2048, d=1024, n=16]; C [b,s,n]; x [b,s,d]; y [b,s,d] fp32.
//
// Mapping: one thread per (b,d,n). lane = n (16 lanes per d, 2 d per warp)
// -> A/B loads per warp per step are one contiguous 128B line (perfect coalescing).
// Serial over s (true data dependence), software-pipelined with U=8 register
// double-buffering to get enough MLP at only ~1.7 warps/SMSP.

#define SSM_S 2048
#define SSM_D 1024
#define SSM_N 16
#define SSM_B 2
#define UNR 8

__global__ void __launch_bounds__(128, 8) ssm_scan_kernel(
    const float* __restrict__ A,
    const float* __restrict__ B,
    const float* __restrict__ C,
    const float* __restrict__ x,
    float* __restrict__ y)
{
    const int t  = blockIdx.x * blockDim.x + threadIdx.x;   // 0 .. 32767
    const int n  = t & (SSM_N - 1);
    const int dd = t >> 4;                                   // 0 .. 2047  (b*d)
    const int b  = dd >> 10;
    const int d  = dd & (SSM_D - 1);

    const size_t abBase = (((size_t)b * SSM_S) * SSM_D + d) * SSM_N + n;
    const float* Ap = A + abBase;
    const float* Bp = B + abBase;
    const float* Cp = C + ((size_t)b * SSM_S) * SSM_N + n;
    const float* xp = x + ((size_t)b * SSM_S) * SSM_D + d;
    float*       yp = y + ((size_t)b * SSM_S) * SSM_D + d;

    const int strAB = SSM_D * SSM_N;   // 16384 floats per step
    const int strX  = SSM_D;           // 1024
    const int strC  = SSM_N;           // 16

    // Prologue: load first U steps
    float a_cur[UNR], g_cur[UNR], x_cur[UNR], c_cur[UNR];
#pragma unroll
    for (int i = 0; i < UNR; ++i) {
        a_cur[i] = __ldcs(Ap + (size_t)i * strAB);   // streaming: no reuse
        g_cur[i] = __ldcs(Bp + (size_t)i * strAB);
        x_cur[i] = __ldcs(xp + i * strX);            // broadcast within 16 lanes
        c_cur[i] = __ldg (Cp + i * strC);            // heavy cross-warp reuse -> cache
    }

    float h = 0.0f;
    const unsigned mask = 0xFFFFFFFFu;
    const bool writer = (n == 0);                    // lanes 0 and 16 write their d

    for (int base = 0; base < SSM_S; base += UNR) {
        const int nb = base + UNR;
        float a_nxt[UNR], g_nxt[UNR], x_nxt[UNR], c_nxt[UNR];
        if (nb < SSM_S) {
#pragma unroll
            for (int i = 0; i < UNR; ++i) {
                a_nxt[i] = __ldcs(Ap + (size_t)(nb + i) * strAB);
                g_nxt[i] = __ldcs(Bp + (size_t)(nb + i) * strAB);
                x_nxt[i] = __ldcs(xp + (nb + i) * strX);
                c_nxt[i] = __ldg (Cp + (nb + i) * strC);
            }
        }

#pragma unroll
        for (int i = 0; i < UNR; ++i) {
            h = fmaf(a_cur[i], h, g_cur[i] * x_cur[i]);   // recurrence (lat-4 chain)
            float p = c_cur[i] * h;
            // reduce over the 16-lane (aligned) n-group
            p += __shfl_xor_sync(mask, p, 8);
            p += __shfl_xor_sync(mask, p, 4);
            p += __shfl_xor_sync(mask, p, 2);
            p += __shfl_xor_sync(mask, p, 1);
            if (writer) yp[(base + i) * strX] = p;
        }

        if (nb < SSM_S) {
#pragma unroll
            for (int i = 0; i < UNR; ++i) {
                a_cur[i] = a_nxt[i];
                g_cur[i] = g_nxt[i];
                x_cur[i] = x_nxt[i];
                c_cur[i] = c_nxt[i];
            }
        }
    }
}

extern "C" void kernel_launch(void* const* d_in, const int* in_sizes, int n_in,
                              void* d_out, int out_size)
{
    const float* A = (const float*)d_in[0];
    const float* B = (const float*)d_in[1];
    const float* C = (const float*)d_in[2];
    const float* x = (const float*)d_in[3];
    float*       y = (float*)d_out;

    const int total_threads = SSM_B * SSM_D * SSM_N;   // 32768
    const int block = 128;
    const int grid  = total_threads / block;           // 256 blocks, one wave
    ssm_scan_kernel<<<grid, block>>>(A, B, C, x, y);
}

// round 4
// speedup vs baseline: 2.3784x; 2.3784x over previous
#include <cuda_runtime.h>
#include <cuda_bf16.h>

// SSM scan: h_t = A_t * h_{t-1} + B_t * x_t ;  y_t[d] = sum_n C_t[n] * h_t[d,n]
// Shapes: A,B [b=2, s=2048, d=1024, n=16]; C [b,s,n]; x [b,s,d]; y [b,s,d] fp32.
//
// Mapping: one thread per (b,d,n). lane = n (16 lanes per d, 2 d per warp)
// -> each A/B load step is one contiguous 128B line per warp (perfect coalescing).
// Serial over s (true dependence); MLP comes from U=8 register double-buffering.
//
// R2 change vs R1: removed the __launch_bounds__ occupancy cap that forced
// 64 regs/thread and spilled the prefetch buffers to local memory. Grid is
// thread-count-limited (32768 threads total => ~256 threads/SM), so up to
// 256 regs/thread are free. block=256, grid=128 => ~1 block/SM.

#define SSM_S 2048
#define SSM_D 1024
#define SSM_N 16
#define SSM_B 2
#define UNR 8

__global__ void __launch_bounds__(256) ssm_scan_kernel(
    const float* __restrict__ A,
    const float* __restrict__ B,
    const float* __restrict__ C,
    const float* __restrict__ x,
    float* __restrict__ y)
{
    const int t  = blockIdx.x * blockDim.x + threadIdx.x;   // 0 .. 32767
    const int n  = t & (SSM_N - 1);
    const int dd = t >> 4;                                   // 0 .. 2047  (b*d)
    const int b  = dd >> 10;
    const int d  = dd & (SSM_D - 1);

    const size_t abBase = (((size_t)b * SSM_S) * SSM_D + d) * SSM_N + n;
    const float* Ap = A + abBase;
    const float* Bp = B + abBase;
    const float* Cp = C + ((size_t)b * SSM_S) * SSM_N + n;
    const float* xp = x + ((size_t)b * SSM_S) * SSM_D + d;
    float*       yp = y + ((size_t)b * SSM_S) * SSM_D + d;

    const int strAB = SSM_D * SSM_N;   // 16384 floats per step
    const int strX  = SSM_D;           // 1024
    const int strC  = SSM_N;           // 16

    // Prologue: load first U steps
    float a_cur[UNR], g_cur[UNR], x_cur[UNR], c_cur[UNR];
#pragma unroll
    for (int i = 0; i < UNR; ++i) {
        a_cur[i] = __ldcs(Ap + (size_t)i * strAB);   // streaming: no reuse
        g_cur[i] = __ldcs(Bp + (size_t)i * strAB);
        x_cur[i] = __ldcs(xp + i * strX);            // broadcast within 16 lanes
        c_cur[i] = __ldg (Cp + i * strC);            // heavy cross-warp reuse -> L2
    }

    float h = 0.0f;
    const unsigned mask = 0xFFFFFFFFu;
    const bool writer = (n == 0);                    // lanes 0 and 16 write their d

    for (int base = 0; base < SSM_S; base += UNR) {
        const int nb = base + UNR;
        float a_nxt[UNR], g_nxt[UNR], x_nxt[UNR], c_nxt[UNR];
        if (nb < SSM_S) {
            // Prefetch next U steps FIRST so these LDGs overlap the compute +
            // the scoreboard waits on the current block's values.
#pragma unroll
            for (int i = 0; i < UNR; ++i) {
                a_nxt[i] = __ldcs(Ap + (size_t)(nb + i) * strAB);
                g_nxt[i] = __ldcs(Bp + (size_t)(nb + i) * strAB);
                x_nxt[i] = __ldcs(xp + (nb + i) * strX);
                c_nxt[i] = __ldg (Cp + (nb + i) * strC);
            }
        }

#pragma unroll
        for (int i = 0; i < UNR; ++i) {
            h = fmaf(a_cur[i], h, g_cur[i] * x_cur[i]);   // recurrence (lat-4 chain)
            float p = c_cur[i] * h;
            // reduce over the 16-lane (aligned) n-group
            p += __shfl_xor_sync(mask, p, 8);
            p += __shfl_xor_sync(mask, p, 4);
            p += __shfl_xor_sync(mask, p, 2);
            p += __shfl_xor_sync(mask, p, 1);
            if (writer) yp[(base + i) * strX] = p;
        }

        if (nb < SSM_S) {
#pragma unroll
            for (int i = 0; i < UNR; ++i) {
                a_cur[i] = a_nxt[i];
                g_cur[i] = g_nxt[i];
                x_cur[i] = x_nxt[i];
                c_cur[i] = c_nxt[i];
            }
        }
    }
}

extern "C" void kernel_launch(void* const* d_in, const int* in_sizes, int n_in,
                              void* d_out, int out_size)
{
    const float* A = (const float*)d_in[0];
    const float* B = (const float*)d_in[1];
    const float* C = (const float*)d_in[2];
    const float* x = (const float*)d_in[3];
    float*       y = (float*)d_out;

    const int total_threads = SSM_B * SSM_D * SSM_N;   // 32768
    const int block = 256;
    const int grid  = total_threads / block;           // 128 blocks
    ssm_scan_kernel<<<grid, block>>>(A, B, C, x, y);
}

// round 6
// speedup vs baseline: 3.0939x; 1.3008x over previous
#include <cuda_runtime.h>
#include <cuda_bf16.h>

// SSM scan: h_t = A_t * h_{t-1} + B_t * x_t ;  y_t[d] = sum_n C_t[n] * h_t[d,n]
// Shapes: A,B [b=2, s=2048, d=1024, n=16]; C [b,s,n]; x [b,s,d]; y [b,s,d] fp32.
//
// Mapping: one thread per (b,d,n). lane = n (16 lanes per d, 2 d per warp)
// -> each A/B load step is one contiguous 128B line per warp.
//
// R5 change vs R4: prefetch DISTANCE 3 (4-slot rotating register buffer,
// loop unrolled by 4) instead of distance 1. R4 measured ~1000cyc exposed
// memory stall per ~1460cyc iteration (issue=30.5%, DRAM=34.7%): distance-1
// tolerance (~1 iteration) < loaded DRAM latency. Distance 3 gives ~3
// iterations (~1400cyc) of tolerance and ~40+ lines/warp in flight
// (~5-6MB chip-wide), enough to go bandwidth-bound.

#define SSM_S 2048
#define SSM_D 1024
#define SSM_N 16
#define SSM_B 2
#define UNR 8
#define NBLK (SSM_S / UNR)   // 256, divisible by 4

__global__ void __launch_bounds__(256) ssm_scan_kernel(
    const float* __restrict__ A,
    const float* __restrict__ B,
    const float* __restrict__ C,
    const float* __restrict__ x,
    float* __restrict__ y)
{
    const int t  = blockIdx.x * blockDim.x + threadIdx.x;   // 0 .. 32767
    const int n  = t & (SSM_N - 1);
    const int dd = t >> 4;                                   // 0 .. 2047  (b*d)
    const int b  = dd >> 10;
    const int d  = dd & (SSM_D - 1);

    const size_t abBase = (((size_t)b * SSM_S) * SSM_D + d) * SSM_N + n;
    const float* Ap = A + abBase;
    const float* Bp = B + abBase;
    const float* Cp = C + ((size_t)b * SSM_S) * SSM_N + n;
    const float* xp = x + ((size_t)b * SSM_S) * SSM_D + d;
    float*       yp = y + ((size_t)b * SSM_S) * SSM_D + d;

    const int strAB = SSM_D * SSM_N;   // 16384 floats per step
    const int strX  = SSM_D;           // 1024
    const int strC  = SSM_N;           // 16

    // 4-slot rotating prefetch buffers (all indices compile-time after unroll
    // -> stay in registers). 4*4*UNR = 128 buffer regs.
    float a_buf[4][UNR], g_buf[4][UNR], x_buf[4][UNR], c_buf[4][UNR];

#define SSM_LOAD(slot, blk)                                                   \
    {                                                                         \
        const int s0 = (blk) * UNR;                                           \
        _Pragma("unroll")                                                     \
        for (int i = 0; i < UNR; ++i) {                                       \
            a_buf[slot][i] = __ldcs(Ap + (size_t)(s0 + i) * strAB);           \
            g_buf[slot][i] = __ldcs(Bp + (size_t)(s0 + i) * strAB);           \
            x_buf[slot][i] = __ldcs(xp + (s0 + i) * strX);                    \
            c_buf[slot][i] = __ldg (Cp + (s0 + i) * strC);                    \
        }                                                                     \
    }

#define SSM_COMPUTE(slot, blk)                                                \
    {                                                                         \
        const int s0 = (blk) * UNR;                                           \
        _Pragma("unroll")                                                     \
        for (int i = 0; i < UNR; ++i) {                                       \
            h = fmaf(a_buf[slot][i], h, g_buf[slot][i] * x_buf[slot][i]);     \
            float p = c_buf[slot][i] * h;                                     \
            p += __shfl_xor_sync(0xFFFFFFFFu, p, 8);                          \
            p += __shfl_xor_sync(0xFFFFFFFFu, p, 4);                          \
            p += __shfl_xor_sync(0xFFFFFFFFu, p, 2);                          \
            p += __shfl_xor_sync(0xFFFFFFFFu, p, 1);                          \
            if (writer) yp[(s0 + i) * strX] = p;                              \
        }                                                                     \
    }

    // Prologue: fill the pipeline 4 blocks deep.
    SSM_LOAD(0, 0)
    SSM_LOAD(1, 1)
    SSM_LOAD(2, 2)
    SSM_LOAD(3, 3)

    float h = 0.0f;
    const bool writer = (n == 0);    // lanes 0 and 16 each write their d

    for (int blk = 0; blk < NBLK; blk += 4) {
        SSM_COMPUTE(0, blk)
        if (blk + 4 < NBLK) SSM_LOAD(0, blk + 4)
        SSM_COMPUTE(1, blk + 1)
        if (blk + 5 < NBLK) SSM_LOAD(1, blk + 5)
        SSM_COMPUTE(2, blk + 2)
        if (blk + 6 < NBLK) SSM_LOAD(2, blk + 6)
        SSM_COMPUTE(3, blk + 3)
        if (blk + 7 < NBLK) SSM_LOAD(3, blk + 7)
    }

#undef SSM_LOAD
#undef SSM_COMPUTE
}

extern "C" void kernel_launch(void* const* d_in, const int* in_sizes, int n_in,
                              void* d_out, int out_size)
{
    const float* A = (const float*)d_in[0];
    const float* B = (const float*)d_in[1];
    const float* C = (const float*)d_in[2];
    const float* x = (const float*)d_in[3];
    float*       y = (float*)d_out;

    const int total_threads = SSM_B * SSM_D * SSM_N;   // 32768
    const int block = 256;
    const int grid  = total_threads / block;           // 128 blocks
    ssm_scan_kernel<<<grid, block>>>(A, B, C, x, y);
}